// round 11
// baseline (speedup 1.0000x reference)
#include <cuda_runtime.h>
#include <cuda_bf16.h>
#include <cstdint>

#define N 4096
#define D 256
#define NBLK 32            // 4096/128 tiles per dim
#define NSLOT 64           // 32 col-blocks * 2 n-warps
#define TILE_HW (128*72)   // halfwords per smem tile stage (stride 72)
#define SMEM_BITS_OFF (4 * TILE_HW)            // halfword offset of bit arrays
#define SMEM_TOTAL (4 * TILE_HW * 2 + 4096)    // bytes: tiles + pm/nm bits

__device__ __align__(16) __nv_bfloat16 g_fnb[(size_t)N * D];   // normalized feats bf16 (2 MB)
__device__ float g_part[3][NSLOT][N];                          // partials: S1, P, NEG (3 MB)
__device__ float g_bsum[64];
__device__ unsigned g_cnt = 0;

// ------------------------- PTX helpers -------------------------------------
__device__ __forceinline__ void ldsm_x4(unsigned &r0, unsigned &r1, unsigned &r2, unsigned &r3, unsigned addr) {
    asm volatile("ldmatrix.sync.aligned.m8n8.x4.shared.b16 {%0,%1,%2,%3}, [%4];"
                 : "=r"(r0), "=r"(r1), "=r"(r2), "=r"(r3) : "r"(addr));
}
__device__ __forceinline__ void mma_bf16(float &c0, float &c1, float &c2, float &c3,
                                         unsigned a0, unsigned a1, unsigned a2, unsigned a3,
                                         unsigned b0, unsigned b1) {
    asm volatile("mma.sync.aligned.m16n8k16.row.col.f32.bf16.bf16.f32 "
                 "{%0,%1,%2,%3},{%4,%5,%6,%7},{%8,%9},{%0,%1,%2,%3};"
                 : "+f"(c0), "+f"(c1), "+f"(c2), "+f"(c3)
                 : "r"(a0), "r"(a1), "r"(a2), "r"(a3), "r"(b0), "r"(b1));
}
#define CP16(dst, src) asm volatile("cp.async.cg.shared.global [%0], [%1], 16;" :: "r"(dst), "l"(src))
#define CPCOMMIT()     asm volatile("cp.async.commit_group;")
#define CPWAIT(n)      asm volatile("cp.async.wait_group %0;" :: "n"(n))
#define BAR_GEMM()     asm volatile("bar.sync 1, 256;" ::: "memory")

// ---------------------------------------------------------------------------
// Kernel B: L2-normalize feature rows -> bf16. 1 warp/row.
// ---------------------------------------------------------------------------
__global__ __launch_bounds__(128) void norm_kernel(const float* __restrict__ f) {
    const int warp = threadIdx.x >> 5;
    const int lane = threadIdx.x & 31;
    const int row  = blockIdx.x * 4 + warp;

    const float4* fr = reinterpret_cast<const float4*>(f + (size_t)row * D) + lane * 2;
    float4 v0 = fr[0];
    float4 v1 = fr[1];

    float s = v0.x*v0.x + v0.y*v0.y + v0.z*v0.z + v0.w*v0.w
            + v1.x*v1.x + v1.y*v1.y + v1.z*v1.z + v1.w*v1.w;
    #pragma unroll
    for (int off = 16; off > 0; off >>= 1)
        s += __shfl_xor_sync(0xffffffffu, s, off);

    const float inv = 1.0f / fmaxf(sqrtf(s), 1e-8f);

    __nv_bfloat162 b0 = __float22bfloat162_rn(make_float2(v0.x*inv, v0.y*inv));
    __nv_bfloat162 b1 = __float22bfloat162_rn(make_float2(v0.z*inv, v0.w*inv));
    __nv_bfloat162 b2 = __float22bfloat162_rn(make_float2(v1.x*inv, v1.y*inv));
    __nv_bfloat162 b3 = __float22bfloat162_rn(make_float2(v1.z*inv, v1.w*inv));

    uint4 u;
    u.x = *reinterpret_cast<unsigned*>(&b0);
    u.y = *reinterpret_cast<unsigned*>(&b1);
    u.z = *reinterpret_cast<unsigned*>(&b2);
    u.w = *reinterpret_cast<unsigned*>(&b3);
    *reinterpret_cast<uint4*>(g_fnb + (size_t)row * D + lane * 8) = u;
}

// ---------------------------------------------------------------------------
// Kernel C: warp-specialized fused kernel. 320 threads:
//   warps 0-7: bf16 mma.sync GEMM (block tile 128x128, cp.async 2-stage)
//   warps 8-9: stream pm/nm float masks -> packed bits in smem (overlaps GEMM)
// Epilogue reads bits from smem (no DRAM), computes S1/P/NEG partials.
// Bit layout per tile row r: word c (c=0..3) bit l  <->  tile col 4*l + c.
// ---------------------------------------------------------------------------
extern __shared__ __align__(16) __nv_bfloat16 dynsmem[];

__global__ __launch_bounds__(320, 2) void main_kernel(const float* __restrict__ pm,
                                                      const float* __restrict__ nm) {
    const int tid   = threadIdx.x;
    const int lane  = tid & 31;
    const int warp  = tid >> 5;
    const int rowBase = blockIdx.y * 128;
    const int colBase = blockIdx.x * 128;

    unsigned* s_pm = reinterpret_cast<unsigned*>(dynsmem + SMEM_BITS_OFF);       // [128][4]
    unsigned* s_nm = s_pm + 512;                                                 // [128][4]

    if (warp >= 8) {
        // ----------------- producer warps: stream + pack masks -----------------
        const int r0w = (warp - 8) * 64;  // rows [r0w, r0w+64)
        #pragma unroll 1
        for (int r0 = r0w; r0 < r0w + 64; r0 += 4) {
            float4 pv[4], nv[4];
            #pragma unroll
            for (int i = 0; i < 4; ++i) {
                const size_t off = (size_t)(rowBase + r0 + i) * N + colBase + 4 * lane;
                pv[i] = *reinterpret_cast<const float4*>(pm + off);
                nv[i] = *reinterpret_cast<const float4*>(nm + off);
            }
            #pragma unroll
            for (int i = 0; i < 4; ++i) {
                const int rowg = rowBase + r0 + i;
                const int cb   = colBase + 4 * lane;
                uint4 pb, nb;
                pb.x = __ballot_sync(0xffffffffu, (pv[i].x != 0.f) && (cb + 0 != rowg));
                pb.y = __ballot_sync(0xffffffffu, (pv[i].y != 0.f) && (cb + 1 != rowg));
                pb.z = __ballot_sync(0xffffffffu, (pv[i].z != 0.f) && (cb + 2 != rowg));
                pb.w = __ballot_sync(0xffffffffu, (pv[i].w != 0.f) && (cb + 3 != rowg));
                nb.x = __ballot_sync(0xffffffffu, (nv[i].x != 0.f) && (cb + 0 != rowg));
                nb.y = __ballot_sync(0xffffffffu, (nv[i].y != 0.f) && (cb + 1 != rowg));
                nb.z = __ballot_sync(0xffffffffu, (nv[i].z != 0.f) && (cb + 2 != rowg));
                nb.w = __ballot_sync(0xffffffffu, (nv[i].w != 0.f) && (cb + 3 != rowg));
                if (lane == 0) {
                    *reinterpret_cast<uint4*>(&s_pm[(r0 + i) * 4]) = pb;
                    *reinterpret_cast<uint4*>(&s_nm[(r0 + i) * 4]) = nb;
                }
            }
        }
        __syncthreads();   // publish bits to GEMM warps
        return;
    }

    // --------------------------- GEMM warps (0-7) ---------------------------
    const int warpM = warp >> 1;   // 0..3
    const int warpN = warp & 1;    // 0..1

    float acc[2][8][4];
    #pragma unroll
    for (int i = 0; i < 2; ++i)
        #pragma unroll
        for (int j = 0; j < 8; ++j)
            #pragma unroll
            for (int k = 0; k < 4; ++k) acc[i][j][k] = 0.f;

    // copy mapping: 2 threads per tile-row, 64B (4x16B) each
    const int ldRow = tid >> 1;
    const int ldK   = (tid & 1) * 32;
    const uint4* fA = reinterpret_cast<const uint4*>(g_fnb + (size_t)(rowBase + ldRow) * D) + (ldK >> 3);
    const uint4* fB = reinterpret_cast<const uint4*>(g_fnb + (size_t)(colBase + ldRow) * D) + (ldK >> 3);

    const unsigned sBase = (unsigned)__cvta_generic_to_shared(dynsmem);
    const unsigned sA0 = sBase;                       // stages 0,1
    const unsigned sB0 = sBase + 2 * TILE_HW * 2;     // stages 0,1
    const unsigned dstA = sA0 + (ldRow * 72 + ldK) * 2;
    const unsigned dstB = sB0 + (ldRow * 72 + ldK) * 2;

#define PREFETCH(kb, s) do {                                            \
        unsigned da = dstA + (s) * TILE_HW * 2;                         \
        unsigned db = dstB + (s) * TILE_HW * 2;                         \
        const uint4* pa = fA + (kb) * 8;                                \
        const uint4* pb = fB + (kb) * 8;                                \
        CP16(da +  0, pa + 0); CP16(db +  0, pb + 0);                   \
        CP16(da + 16, pa + 1); CP16(db + 16, pb + 1);                   \
        CP16(da + 32, pa + 2); CP16(db + 32, pb + 2);                   \
        CP16(da + 48, pa + 3); CP16(db + 48, pb + 3);                   \
        CPCOMMIT();                                                     \
    } while (0)

    // ldmatrix per-lane address components
    const int aRow = (lane & 7) + ((lane & 8)  ? 8 : 0);
    const int aK8  = (lane & 16) ? 8 : 0;
    const int bRow = (lane & 7) + ((lane & 16) ? 8 : 0);
    const int bK8  = (lane & 8)  ? 8 : 0;

    PREFETCH(0, 0);
    PREFETCH(1, 1);

    #pragma unroll
    for (int kb = 0; kb < 4; ++kb) {
        if (kb == 3) { CPWAIT(0); } else { CPWAIT(1); }
        BAR_GEMM();

        const unsigned sA = sA0 + (kb & 1) * TILE_HW * 2;
        const unsigned sB = sB0 + (kb & 1) * TILE_HW * 2;

        #pragma unroll
        for (int kk = 0; kk < 4; ++kk) {
            unsigned a[2][4];
            #pragma unroll
            for (int mt = 0; mt < 2; ++mt) {
                unsigned addr = sA + ((warpM * 32 + mt * 16 + aRow) * 72 + kk * 16 + aK8) * 2;
                ldsm_x4(a[mt][0], a[mt][1], a[mt][2], a[mt][3], addr);
            }
            #pragma unroll
            for (int p = 0; p < 4; ++p) {
                unsigned b0, b1, b2, b3;
                unsigned addr = sB + ((warpN * 64 + p * 16 + bRow) * 72 + kk * 16 + bK8) * 2;
                ldsm_x4(b0, b1, b2, b3, addr);
                #pragma unroll
                for (int mt = 0; mt < 2; ++mt) {
                    mma_bf16(acc[mt][2*p  ][0], acc[mt][2*p  ][1], acc[mt][2*p  ][2], acc[mt][2*p  ][3],
                             a[mt][0], a[mt][1], a[mt][2], a[mt][3], b0, b1);
                    mma_bf16(acc[mt][2*p+1][0], acc[mt][2*p+1][1], acc[mt][2*p+1][2], acc[mt][2*p+1][3],
                             a[mt][0], a[mt][1], a[mt][2], a[mt][3], b2, b3);
                }
            }
        }
        BAR_GEMM();
        if (kb < 2) {
            if (kb == 0) PREFETCH(2, 0); else PREFETCH(3, 1);
        }
    }
#undef PREFETCH

    __syncthreads();   // join with producers: bits are ready

    // ---- epilogue: read packed bits from smem, accumulate S1 / P / NEG ----
    const float INV_T = 1.0f / 0.07f;
    const int g  = lane >> 2;
    const int t4 = lane & 3;
    const int c0 = (t4 & 1) * 2;
    const int bsh = warpN * 16 + (t4 >> 1);

    float S1[4] = {0.f, 0.f, 0.f, 0.f};
    float P [4] = {0.f, 0.f, 0.f, 0.f};
    float NG[4] = {0.f, 0.f, 0.f, 0.f};

    #pragma unroll
    for (int mt = 0; mt < 2; ++mt) {
        #pragma unroll
        for (int hi = 0; hi < 2; ++hi) {
            const int ri = mt * 2 + hi;
            const int r  = warpM * 32 + mt * 16 + hi * 8 + g;  // tile-local row
            const uint2 pw = *reinterpret_cast<const uint2*>(&s_pm[r * 4 + c0]);
            const uint2 nw = *reinterpret_cast<const uint2*>(&s_nm[r * 4 + c0]);
            #pragma unroll
            for (int nt = 0; nt < 8; ++nt) {
                const int bit = bsh + nt * 2;
                const float p0 = (float)((pw.x >> bit) & 1u);
                const float p1 = (float)((pw.y >> bit) & 1u);
                const float n0 = (float)((nw.x >> bit) & 1u);
                const float n1 = (float)((nw.y >> bit) & 1u);
                const float z0 = acc[mt][nt][hi * 2 + 0] * INV_T;
                const float z1 = acc[mt][nt][hi * 2 + 1] * INV_T;
                S1[ri] += p0 * z0 + p1 * z1;
                P [ri] += p0 + p1;
                NG[ri] += n0 * __expf(z0) + n1 * __expf(z1);
            }
        }
    }

    #pragma unroll
    for (int ri = 0; ri < 4; ++ri) {
        S1[ri] += __shfl_xor_sync(0xffffffffu, S1[ri], 1);
        S1[ri] += __shfl_xor_sync(0xffffffffu, S1[ri], 2);
        P [ri] += __shfl_xor_sync(0xffffffffu, P [ri], 1);
        P [ri] += __shfl_xor_sync(0xffffffffu, P [ri], 2);
        NG[ri] += __shfl_xor_sync(0xffffffffu, NG[ri], 1);
        NG[ri] += __shfl_xor_sync(0xffffffffu, NG[ri], 2);
    }

    if (t4 == 0) {
        const int cs = blockIdx.x * 2 + warpN;
        #pragma unroll
        for (int ri = 0; ri < 4; ++ri) {
            const int mt = ri >> 1, hi = ri & 1;
            const int grow = rowBase + warpM * 32 + mt * 16 + hi * 8 + g;
            g_part[0][cs][grow] = S1[ri];
            g_part[1][cs][grow] = P[ri];
            g_part[2][cs][grow] = NG[ri];
        }
    }
}

// ---------------------------------------------------------------------------
// Kernel D: per-row finalize + full reduction (last block finishes).
// 64 blocks x 256 threads: 64 rows/block, 4 slot-groups of 16 per row.
// ---------------------------------------------------------------------------
__global__ __launch_bounds__(256) void finalize_kernel(float* __restrict__ out) {
    const int r   = threadIdx.x & 63;          // row within block
    const int p   = threadIdx.x >> 6;          // slot group 0..3
    const int row = blockIdx.x * 64 + r;

    float s1 = 0.f, pp = 0.f, ng = 0.f;
    #pragma unroll
    for (int c = p * 16; c < p * 16 + 16; ++c) {
        s1 += g_part[0][c][row];
        pp += g_part[1][c][row];
        ng += g_part[2][c][row];
    }

    __shared__ float sh[3][4][64];
    sh[0][p][r] = s1; sh[1][p][r] = pp; sh[2][p][r] = ng;
    __syncthreads();

    __shared__ float st[64];
    if (p == 0) {
        s1 = sh[0][0][r] + sh[0][1][r] + sh[0][2][r] + sh[0][3][r];
        pp = sh[1][0][r] + sh[1][1][r] + sh[1][2][r] + sh[1][3][r];
        ng = sh[2][0][r] + sh[2][1][r] + sh[2][2][r] + sh[2][3][r];
        float term = 0.f;
        if (pp > 0.5f) term = (s1 - pp * logf(ng)) / pp;
        st[r] = term;
    }
    __syncthreads();

    __shared__ unsigned s_last;
    if (threadIdx.x < 32) {
        float v = st[threadIdx.x] + st[threadIdx.x + 32];
        #pragma unroll
        for (int off = 16; off > 0; off >>= 1)
            v += __shfl_xor_sync(0xffffffffu, v, off);
        if (threadIdx.x == 0) {
            g_bsum[blockIdx.x] = v;
            __threadfence();
            s_last = atomicAdd(&g_cnt, 1u);
        }
    }
    __syncthreads();

    if (s_last == 63 && threadIdx.x < 32) {
        __threadfence();
        volatile float* vb = g_bsum;
        float v = vb[threadIdx.x] + vb[threadIdx.x + 32];
        #pragma unroll
        for (int off = 16; off > 0; off >>= 1)
            v += __shfl_xor_sync(0xffffffffu, v, off);
        if (threadIdx.x == 0) {
            out[0] = -(v / (float)N);
            g_cnt = 0;   // reset for next graph replay
        }
    }
}

// ---------------------------------------------------------------------------
extern "C" void kernel_launch(void* const* d_in, const int* in_sizes, int n_in,
                              void* d_out, int out_size) {
    (void)in_sizes; (void)n_in; (void)out_size;
    const float* f  = (const float*)d_in[0];
    const float* pm = (const float*)d_in[1];
    const float* nm = (const float*)d_in[2];

    static bool attr_set = false;
    if (!attr_set) {
        cudaFuncSetAttribute(main_kernel, cudaFuncAttributeMaxDynamicSharedMemorySize,
                             SMEM_TOTAL);
        attr_set = true;
    }

    norm_kernel<<<N / 4, 128>>>(f);
    dim3 grid(NBLK, NBLK);
    main_kernel<<<grid, 320, SMEM_TOTAL>>>(pm, nm);
    finalize_kernel<<<64, 256>>>((float*)d_out);
}

// round 12
// speedup vs baseline: 1.2331x; 1.2331x over previous
#include <cuda_runtime.h>
#include <cuda_bf16.h>
#include <cstdint>

#define N 4096
#define D 256
#define NBLK 32            // 4096/128 tiles per dim
#define NSLOT 64           // 32 col-blocks * 2 n-warps
#define TILE_HW (128*72)   // halfwords per smem tile stage (stride 72)

__device__ __align__(16) __nv_bfloat16 g_fnb[(size_t)N * D];   // normalized feats bf16 (2 MB)
__device__ float g_part[3][NSLOT][N];                          // partials: S1, P, NEG (3 MB)
__device__ float g_bsum[64];
__device__ unsigned g_cnt = 0;

// ------------------------- PTX helpers -------------------------------------
__device__ __forceinline__ void ldsm_x4(unsigned &r0, unsigned &r1, unsigned &r2, unsigned &r3, unsigned addr) {
    asm volatile("ldmatrix.sync.aligned.m8n8.x4.shared.b16 {%0,%1,%2,%3}, [%4];"
                 : "=r"(r0), "=r"(r1), "=r"(r2), "=r"(r3) : "r"(addr));
}
__device__ __forceinline__ void mma_bf16(float &c0, float &c1, float &c2, float &c3,
                                         unsigned a0, unsigned a1, unsigned a2, unsigned a3,
                                         unsigned b0, unsigned b1) {
    asm volatile("mma.sync.aligned.m16n8k16.row.col.f32.bf16.bf16.f32 "
                 "{%0,%1,%2,%3},{%4,%5,%6,%7},{%8,%9},{%0,%1,%2,%3};"
                 : "+f"(c0), "+f"(c1), "+f"(c2), "+f"(c3)
                 : "r"(a0), "r"(a1), "r"(a2), "r"(a3), "r"(b0), "r"(b1));
}
#define CP16(dst, src) asm volatile("cp.async.cg.shared.global [%0], [%1], 16;" :: "r"(dst), "l"(src))
#define CPCOMMIT()     asm volatile("cp.async.commit_group;")
#define CPWAIT(n)      asm volatile("cp.async.wait_group %0;" :: "n"(n))
#define PF_L2(p)       asm volatile("prefetch.global.L2 [%0];" :: "l"(p))

// ---------------------------------------------------------------------------
// Kernel B: L2-normalize feature rows -> bf16. 2 rows per warp (MLP=4).
// ---------------------------------------------------------------------------
__global__ __launch_bounds__(256) void norm_kernel(const float* __restrict__ f) {
    const int warp = threadIdx.x >> 5;
    const int lane = threadIdx.x & 31;
    const int row0 = blockIdx.x * 16 + warp * 2;

    const float4* fr0 = reinterpret_cast<const float4*>(f + (size_t)row0 * D) + lane * 2;
    const float4* fr1 = reinterpret_cast<const float4*>(f + (size_t)(row0 + 1) * D) + lane * 2;
    float4 a0 = fr0[0], a1 = fr0[1];
    float4 b0 = fr1[0], b1 = fr1[1];

    float sa = a0.x*a0.x + a0.y*a0.y + a0.z*a0.z + a0.w*a0.w
             + a1.x*a1.x + a1.y*a1.y + a1.z*a1.z + a1.w*a1.w;
    float sb = b0.x*b0.x + b0.y*b0.y + b0.z*b0.z + b0.w*b0.w
             + b1.x*b1.x + b1.y*b1.y + b1.z*b1.z + b1.w*b1.w;
    #pragma unroll
    for (int off = 16; off > 0; off >>= 1) {
        sa += __shfl_xor_sync(0xffffffffu, sa, off);
        sb += __shfl_xor_sync(0xffffffffu, sb, off);
    }
    const float ia = 1.0f / fmaxf(sqrtf(sa), 1e-8f);
    const float ib = 1.0f / fmaxf(sqrtf(sb), 1e-8f);

    uint4 ua, ub;
    {
        __nv_bfloat162 c0 = __float22bfloat162_rn(make_float2(a0.x*ia, a0.y*ia));
        __nv_bfloat162 c1 = __float22bfloat162_rn(make_float2(a0.z*ia, a0.w*ia));
        __nv_bfloat162 c2 = __float22bfloat162_rn(make_float2(a1.x*ia, a1.y*ia));
        __nv_bfloat162 c3 = __float22bfloat162_rn(make_float2(a1.z*ia, a1.w*ia));
        ua.x = *reinterpret_cast<unsigned*>(&c0);
        ua.y = *reinterpret_cast<unsigned*>(&c1);
        ua.z = *reinterpret_cast<unsigned*>(&c2);
        ua.w = *reinterpret_cast<unsigned*>(&c3);
    }
    {
        __nv_bfloat162 c0 = __float22bfloat162_rn(make_float2(b0.x*ib, b0.y*ib));
        __nv_bfloat162 c1 = __float22bfloat162_rn(make_float2(b0.z*ib, b0.w*ib));
        __nv_bfloat162 c2 = __float22bfloat162_rn(make_float2(b1.x*ib, b1.y*ib));
        __nv_bfloat162 c3 = __float22bfloat162_rn(make_float2(b1.z*ib, b1.w*ib));
        ub.x = *reinterpret_cast<unsigned*>(&c0);
        ub.y = *reinterpret_cast<unsigned*>(&c1);
        ub.z = *reinterpret_cast<unsigned*>(&c2);
        ub.w = *reinterpret_cast<unsigned*>(&c3);
    }
    *reinterpret_cast<uint4*>(g_fnb + (size_t)row0 * D + lane * 8) = ua;
    *reinterpret_cast<uint4*>(g_fnb + (size_t)(row0 + 1) * D + lane * 8) = ub;
}

// ---------------------------------------------------------------------------
// Kernel C: cosim GEMM (bf16 mma.sync, 2-stage cp.async pipeline) + fused
// float-mask epilogue. L2 prefetch of the CTA's mask tiles is issued at CTA
// start so the DRAM->L2 transfer overlaps the HMMA mainloop; epilogue LDGs
// then hit L2. Block 128x128, 8 warps (4M x 2N), warp tile 32x64, K in 4x64.
// ---------------------------------------------------------------------------
extern __shared__ __align__(16) __nv_bfloat16 dynsmem[];

__global__ __launch_bounds__(256, 2) void main_kernel(const float* __restrict__ pm,
                                                      const float* __restrict__ nm) {
    const int tid   = threadIdx.x;
    const int lane  = tid & 31;
    const int warp  = tid >> 5;
    const int warpM = warp >> 1;   // 0..3
    const int warpN = warp & 1;    // 0..1
    const int rowBase = blockIdx.y * 128;
    const int colBase = blockIdx.x * 128;

    // ---- L2 prefetch of this CTA's 131 KB mask working set (no regs held) ----
    {
        const int r = tid >> 1;                 // 0..127
        const int h = (tid & 1) * 64;           // half-row (64 floats = 2 lines)
        const float* pp = pm + (size_t)(rowBase + r) * N + colBase + h;
        const float* np = nm + (size_t)(rowBase + r) * N + colBase + h;
        PF_L2(pp); PF_L2(pp + 32);
        PF_L2(np); PF_L2(np + 32);
    }

    float acc[2][8][4];
    #pragma unroll
    for (int i = 0; i < 2; ++i)
        #pragma unroll
        for (int j = 0; j < 8; ++j)
            #pragma unroll
            for (int k = 0; k < 4; ++k) acc[i][j][k] = 0.f;

    // copy mapping: 2 threads per tile-row, 64B (4x16B) each
    const int ldRow = tid >> 1;
    const int ldK   = (tid & 1) * 32;
    const uint4* fA = reinterpret_cast<const uint4*>(g_fnb + (size_t)(rowBase + ldRow) * D) + (ldK >> 3);
    const uint4* fB = reinterpret_cast<const uint4*>(g_fnb + (size_t)(colBase + ldRow) * D) + (ldK >> 3);

    const unsigned sBase = (unsigned)__cvta_generic_to_shared(dynsmem);
    const unsigned sA0 = sBase;                       // stages 0,1
    const unsigned sB0 = sBase + 2 * TILE_HW * 2;     // stages 0,1
    const unsigned dstA = sA0 + (ldRow * 72 + ldK) * 2;
    const unsigned dstB = sB0 + (ldRow * 72 + ldK) * 2;

#define PREFETCH(kb, s) do {                                            \
        unsigned da = dstA + (s) * TILE_HW * 2;                         \
        unsigned db = dstB + (s) * TILE_HW * 2;                         \
        const uint4* pa = fA + (kb) * 8;                                \
        const uint4* pb = fB + (kb) * 8;                                \
        CP16(da +  0, pa + 0); CP16(db +  0, pb + 0);                   \
        CP16(da + 16, pa + 1); CP16(db + 16, pb + 1);                   \
        CP16(da + 32, pa + 2); CP16(db + 32, pb + 2);                   \
        CP16(da + 48, pa + 3); CP16(db + 48, pb + 3);                   \
        CPCOMMIT();                                                     \
    } while (0)

    // ldmatrix per-lane address components
    const int aRow = (lane & 7) + ((lane & 8)  ? 8 : 0);
    const int aK8  = (lane & 16) ? 8 : 0;
    const int bRow = (lane & 7) + ((lane & 16) ? 8 : 0);
    const int bK8  = (lane & 8)  ? 8 : 0;

    PREFETCH(0, 0);
    PREFETCH(1, 1);

    #pragma unroll
    for (int kb = 0; kb < 4; ++kb) {
        if (kb == 3) { CPWAIT(0); } else { CPWAIT(1); }
        __syncthreads();

        const unsigned sA = sA0 + (kb & 1) * TILE_HW * 2;
        const unsigned sB = sB0 + (kb & 1) * TILE_HW * 2;

        #pragma unroll
        for (int kk = 0; kk < 4; ++kk) {
            unsigned b[4][4];
            #pragma unroll
            for (int p = 0; p < 4; ++p) {
                unsigned addr = sB + ((warpN * 64 + p * 16 + bRow) * 72 + kk * 16 + bK8) * 2;
                ldsm_x4(b[p][0], b[p][1], b[p][2], b[p][3], addr);
            }
            unsigned a[2][4];
            #pragma unroll
            for (int mt = 0; mt < 2; ++mt) {
                unsigned addr = sA + ((warpM * 32 + mt * 16 + aRow) * 72 + kk * 16 + aK8) * 2;
                ldsm_x4(a[mt][0], a[mt][1], a[mt][2], a[mt][3], addr);
            }
            #pragma unroll
            for (int mt = 0; mt < 2; ++mt)
                #pragma unroll
                for (int p = 0; p < 4; ++p) {
                    mma_bf16(acc[mt][2*p  ][0], acc[mt][2*p  ][1], acc[mt][2*p  ][2], acc[mt][2*p  ][3],
                             a[mt][0], a[mt][1], a[mt][2], a[mt][3], b[p][0], b[p][1]);
                    mma_bf16(acc[mt][2*p+1][0], acc[mt][2*p+1][1], acc[mt][2*p+1][2], acc[mt][2*p+1][3],
                             a[mt][0], a[mt][1], a[mt][2], a[mt][3], b[p][2], b[p][3]);
                }
        }
        __syncthreads();
        if (kb < 2) {
            if (kb == 0) PREFETCH(2, 0); else PREFETCH(3, 1);
        }
    }
#undef PREFETCH

    // ---- epilogue: mask loads (L2-warm), accumulate per-row S1 / P / NEG ----
    const float INV_T = 1.0f / 0.07f;
    const int g  = lane >> 2;
    const int t4 = lane & 3;

    float S1[4] = {0.f, 0.f, 0.f, 0.f};
    float P [4] = {0.f, 0.f, 0.f, 0.f};
    float NG[4] = {0.f, 0.f, 0.f, 0.f};

    #pragma unroll
    for (int mt = 0; mt < 2; ++mt) {
        #pragma unroll
        for (int hi = 0; hi < 2; ++hi) {
            const int ri   = mt * 2 + hi;
            const int grow = rowBase + warpM * 32 + mt * 16 + hi * 8 + g;
            const float* pmRow = pm + (size_t)grow * N;
            const float* nmRow = nm + (size_t)grow * N;
            // issue all 16 loads first (MLP), then math
            float2 pv[8], nv[8];
            #pragma unroll
            for (int nt = 0; nt < 8; ++nt) {
                const int gcol = colBase + warpN * 64 + nt * 8 + t4 * 2;
                pv[nt] = *reinterpret_cast<const float2*>(pmRow + gcol);
                nv[nt] = *reinterpret_cast<const float2*>(nmRow + gcol);
            }
            #pragma unroll
            for (int nt = 0; nt < 8; ++nt) {
                const int gcol = colBase + warpN * 64 + nt * 8 + t4 * 2;
                float p0 = pv[nt].x, p1 = pv[nt].y;
                float n0 = nv[nt].x, n1 = nv[nt].y;
                if (grow == gcol)     { p0 = 0.f; n0 = 0.f; }
                if (grow == gcol + 1) { p1 = 0.f; n1 = 0.f; }
                const float z0 = acc[mt][nt][hi * 2 + 0] * INV_T;
                const float z1 = acc[mt][nt][hi * 2 + 1] * INV_T;
                S1[ri] += p0 * z0 + p1 * z1;
                P [ri] += p0 + p1;
                NG[ri] += n0 * __expf(z0) + n1 * __expf(z1);
            }
        }
    }

    // reduce across the 4 lanes sharing each row
    #pragma unroll
    for (int ri = 0; ri < 4; ++ri) {
        S1[ri] += __shfl_xor_sync(0xffffffffu, S1[ri], 1);
        S1[ri] += __shfl_xor_sync(0xffffffffu, S1[ri], 2);
        P [ri] += __shfl_xor_sync(0xffffffffu, P [ri], 1);
        P [ri] += __shfl_xor_sync(0xffffffffu, P [ri], 2);
        NG[ri] += __shfl_xor_sync(0xffffffffu, NG[ri], 1);
        NG[ri] += __shfl_xor_sync(0xffffffffu, NG[ri], 2);
    }

    if (t4 == 0) {
        const int cs = blockIdx.x * 2 + warpN;
        #pragma unroll
        for (int ri = 0; ri < 4; ++ri) {
            const int mt = ri >> 1, hi = ri & 1;
            const int grow = rowBase + warpM * 32 + mt * 16 + hi * 8 + g;
            g_part[0][cs][grow] = S1[ri];
            g_part[1][cs][grow] = P[ri];
            g_part[2][cs][grow] = NG[ri];
        }
    }
}

// ---------------------------------------------------------------------------
// Kernel D: per-row finalize + full reduction (last block finishes).
// 64 blocks x 256 threads: 64 rows/block, 4 slot-groups of 16 per row.
// ---------------------------------------------------------------------------
__global__ __launch_bounds__(256) void finalize_kernel(float* __restrict__ out) {
    const int r   = threadIdx.x & 63;          // row within block
    const int p   = threadIdx.x >> 6;          // slot group 0..3
    const int row = blockIdx.x * 64 + r;

    float s1 = 0.f, pp = 0.f, ng = 0.f;
    #pragma unroll
    for (int c = p * 16; c < p * 16 + 16; ++c) {
        s1 += g_part[0][c][row];
        pp += g_part[1][c][row];
        ng += g_part[2][c][row];
    }

    __shared__ float sh[3][4][64];
    sh[0][p][r] = s1; sh[1][p][r] = pp; sh[2][p][r] = ng;
    __syncthreads();

    __shared__ float st[64];
    if (p == 0) {
        s1 = sh[0][0][r] + sh[0][1][r] + sh[0][2][r] + sh[0][3][r];
        pp = sh[1][0][r] + sh[1][1][r] + sh[1][2][r] + sh[1][3][r];
        ng = sh[2][0][r] + sh[2][1][r] + sh[2][2][r] + sh[2][3][r];
        float term = 0.f;
        if (pp > 0.5f) term = (s1 - pp * logf(ng)) / pp;
        st[r] = term;
    }
    __syncthreads();

    __shared__ unsigned s_last;
    if (threadIdx.x < 32) {
        float v = st[threadIdx.x] + st[threadIdx.x + 32];
        #pragma unroll
        for (int off = 16; off > 0; off >>= 1)
            v += __shfl_xor_sync(0xffffffffu, v, off);
        if (threadIdx.x == 0) {
            g_bsum[blockIdx.x] = v;
            __threadfence();
            s_last = atomicAdd(&g_cnt, 1u);
        }
    }
    __syncthreads();

    if (s_last == 63 && threadIdx.x < 32) {
        __threadfence();
        volatile float* vb = g_bsum;
        float v = vb[threadIdx.x] + vb[threadIdx.x + 32];
        #pragma unroll
        for (int off = 16; off > 0; off >>= 1)
            v += __shfl_xor_sync(0xffffffffu, v, off);
        if (threadIdx.x == 0) {
            out[0] = -(v / (float)N);
            g_cnt = 0;   // reset for next graph replay
        }
    }
}

// ---------------------------------------------------------------------------
extern "C" void kernel_launch(void* const* d_in, const int* in_sizes, int n_in,
                              void* d_out, int out_size) {
    (void)in_sizes; (void)n_in; (void)out_size;
    const float* f  = (const float*)d_in[0];
    const float* pm = (const float*)d_in[1];
    const float* nm = (const float*)d_in[2];

    static bool attr_set = false;
    if (!attr_set) {
        cudaFuncSetAttribute(main_kernel, cudaFuncAttributeMaxDynamicSharedMemorySize,
                             4 * TILE_HW * 2);
        attr_set = true;
    }

    norm_kernel<<<N / 16, 256>>>(f);
    dim3 grid(NBLK, NBLK);
    main_kernel<<<grid, 256, 4 * TILE_HW * 2>>>(pm, nm);
    finalize_kernel<<<64, 256>>>((float*)d_out);
}

// round 16
// speedup vs baseline: 1.3835x; 1.1220x over previous
#include <cuda_runtime.h>
#include <cuda_bf16.h>
#include <cstdint>

#define N 4096
#define D 256
#define NBLK 32            // 4096/128 tiles per dim
#define NSLOT 64           // 32 col-blocks * 2 halves
#define NCTA (NBLK * (NBLK + 1) / 2)   // 528 upper-triangle tiles
#define TILE_HW (128*72)   // halfwords per smem tile stage (stride 72)
#define ZSTR 130           // fp32 stride of z tile in smem (even, low-conflict)

__device__ __align__(16) __nv_bfloat16 g_fnb[(size_t)N * D];   // normalized feats bf16 (2 MB)
__device__ float g_part[3][NSLOT][N];                          // partials: S1, P, NEG (3 MB)
__device__ float g_bsum[64];
__device__ unsigned g_cnt = 0;

// ------------------------- PTX helpers -------------------------------------
__device__ __forceinline__ void ldsm_x4(unsigned &r0, unsigned &r1, unsigned &r2, unsigned &r3, unsigned addr) {
    asm volatile("ldmatrix.sync.aligned.m8n8.x4.shared.b16 {%0,%1,%2,%3}, [%4];"
                 : "=r"(r0), "=r"(r1), "=r"(r2), "=r"(r3) : "r"(addr));
}
__device__ __forceinline__ void mma_bf16(float &c0, float &c1, float &c2, float &c3,
                                         unsigned a0, unsigned a1, unsigned a2, unsigned a3,
                                         unsigned b0, unsigned b1) {
    asm volatile("mma.sync.aligned.m16n8k16.row.col.f32.bf16.bf16.f32 "
                 "{%0,%1,%2,%3},{%4,%5,%6,%7},{%8,%9},{%0,%1,%2,%3};"
                 : "+f"(c0), "+f"(c1), "+f"(c2), "+f"(c3)
                 : "r"(a0), "r"(a1), "r"(a2), "r"(a3), "r"(b0), "r"(b1));
}
#define CP16(dst, src) asm volatile("cp.async.cg.shared.global [%0], [%1], 16;" :: "r"(dst), "l"(src))
#define CPCOMMIT()     asm volatile("cp.async.commit_group;")
#define CPWAIT(n)      asm volatile("cp.async.wait_group %0;" :: "n"(n))

// ---------------------------------------------------------------------------
// Kernel B: L2-normalize feature rows -> bf16. 1 warp/row (R10 version).
// ---------------------------------------------------------------------------
__global__ __launch_bounds__(128) void norm_kernel(const float* __restrict__ f) {
    const int warp = threadIdx.x >> 5;
    const int lane = threadIdx.x & 31;
    const int row  = blockIdx.x * 4 + warp;

    const float4* fr = reinterpret_cast<const float4*>(f + (size_t)row * D) + lane * 2;
    float4 v0 = fr[0];
    float4 v1 = fr[1];

    float s = v0.x*v0.x + v0.y*v0.y + v0.z*v0.z + v0.w*v0.w
            + v1.x*v1.x + v1.y*v1.y + v1.z*v1.z + v1.w*v1.w;
    #pragma unroll
    for (int off = 16; off > 0; off >>= 1)
        s += __shfl_xor_sync(0xffffffffu, s, off);

    const float inv = 1.0f / fmaxf(sqrtf(s), 1e-8f);

    __nv_bfloat162 b0 = __float22bfloat162_rn(make_float2(v0.x*inv, v0.y*inv));
    __nv_bfloat162 b1 = __float22bfloat162_rn(make_float2(v0.z*inv, v0.w*inv));
    __nv_bfloat162 b2 = __float22bfloat162_rn(make_float2(v1.x*inv, v1.y*inv));
    __nv_bfloat162 b3 = __float22bfloat162_rn(make_float2(v1.z*inv, v1.w*inv));

    uint4 u;
    u.x = *reinterpret_cast<unsigned*>(&b0);
    u.y = *reinterpret_cast<unsigned*>(&b1);
    u.z = *reinterpret_cast<unsigned*>(&b2);
    u.w = *reinterpret_cast<unsigned*>(&b3);
    *reinterpret_cast<uint4*>(g_fnb + (size_t)row * D + lane * 8) = u;
}

// ---------------------------------------------------------------------------
// Kernel C: upper-triangle cosim GEMM (symmetry: z[i][j]=z[j][i]) + two-pass
// mask epilogue.  528 CTAs, tile (bi,bj) with bj >= bi.
//   pass 1: rows of bi, mask tile (bi,bj), z from registers (as R10)
//   pass 2 (bj>bi): rows of bj, mask tile (bj,bi), z^T read from smem zs
// Slots: row r gets col-block half c-half exactly once across all CTAs.
// ---------------------------------------------------------------------------
extern __shared__ __align__(16) __nv_bfloat16 dynsmem[];

__global__ __launch_bounds__(256, 2) void main_kernel(const float* __restrict__ pm,
                                                      const float* __restrict__ nm) {
    // linear -> upper-triangle (bi, bj)
    int bi = 0, rem = blockIdx.x;
    while (rem >= NBLK - bi) { rem -= NBLK - bi; ++bi; }
    const int bj = bi + rem;
    const bool offdiag = (bj > bi);

    const int tid   = threadIdx.x;
    const int lane  = tid & 31;
    const int warp  = tid >> 5;
    const int warpM = warp >> 1;   // 0..3
    const int warpN = warp & 1;    // 0..1
    const int rowBase = bi * 128;
    const int colBase = bj * 128;

    float acc[2][8][4];
    #pragma unroll
    for (int i = 0; i < 2; ++i)
        #pragma unroll
        for (int j = 0; j < 8; ++j)
            #pragma unroll
            for (int k = 0; k < 4; ++k) acc[i][j][k] = 0.f;

    // copy mapping: 2 threads per tile-row, 64B (4x16B) each
    const int ldRow = tid >> 1;
    const int ldK   = (tid & 1) * 32;
    const uint4* fA = reinterpret_cast<const uint4*>(g_fnb + (size_t)(rowBase + ldRow) * D) + (ldK >> 3);
    const uint4* fB = reinterpret_cast<const uint4*>(g_fnb + (size_t)(colBase + ldRow) * D) + (ldK >> 3);

    const unsigned sBase = (unsigned)__cvta_generic_to_shared(dynsmem);
    const unsigned sA0 = sBase;                       // stages 0,1
    const unsigned sB0 = sBase + 2 * TILE_HW * 2;     // stages 0,1
    const unsigned dstA = sA0 + (ldRow * 72 + ldK) * 2;
    const unsigned dstB = sB0 + (ldRow * 72 + ldK) * 2;

#define PREFETCH(kb, s) do {                                            \
        unsigned da = dstA + (s) * TILE_HW * 2;                         \
        unsigned db = dstB + (s) * TILE_HW * 2;                         \
        const uint4* pa = fA + (kb) * 8;                                \
        const uint4* pb = fB + (kb) * 8;                                \
        CP16(da +  0, pa + 0); CP16(db +  0, pb + 0);                   \
        CP16(da + 16, pa + 1); CP16(db + 16, pb + 1);                   \
        CP16(da + 32, pa + 2); CP16(db + 32, pb + 2);                   \
        CP16(da + 48, pa + 3); CP16(db + 48, pb + 3);                   \
        CPCOMMIT();                                                     \
    } while (0)

    // ldmatrix per-lane address components
    const int aRow = (lane & 7) + ((lane & 8)  ? 8 : 0);
    const int aK8  = (lane & 16) ? 8 : 0;
    const int bRow = (lane & 7) + ((lane & 16) ? 8 : 0);
    const int bK8  = (lane & 8)  ? 8 : 0;

    PREFETCH(0, 0);
    PREFETCH(1, 1);

    #pragma unroll
    for (int kb = 0; kb < 4; ++kb) {
        if (kb == 3) { CPWAIT(0); } else { CPWAIT(1); }
        __syncthreads();

        const unsigned sA = sA0 + (kb & 1) * TILE_HW * 2;
        const unsigned sB = sB0 + (kb & 1) * TILE_HW * 2;

        #pragma unroll
        for (int kk = 0; kk < 4; ++kk) {
            unsigned b[4][4];
            #pragma unroll
            for (int p = 0; p < 4; ++p) {
                unsigned addr = sB + ((warpN * 64 + p * 16 + bRow) * 72 + kk * 16 + bK8) * 2;
                ldsm_x4(b[p][0], b[p][1], b[p][2], b[p][3], addr);
            }
            unsigned a[2][4];
            #pragma unroll
            for (int mt = 0; mt < 2; ++mt) {
                unsigned addr = sA + ((warpM * 32 + mt * 16 + aRow) * 72 + kk * 16 + aK8) * 2;
                ldsm_x4(a[mt][0], a[mt][1], a[mt][2], a[mt][3], addr);
            }
            #pragma unroll
            for (int mt = 0; mt < 2; ++mt)
                #pragma unroll
                for (int p = 0; p < 4; ++p) {
                    mma_bf16(acc[mt][2*p  ][0], acc[mt][2*p  ][1], acc[mt][2*p  ][2], acc[mt][2*p  ][3],
                             a[mt][0], a[mt][1], a[mt][2], a[mt][3], b[p][0], b[p][1]);
                    mma_bf16(acc[mt][2*p+1][0], acc[mt][2*p+1][1], acc[mt][2*p+1][2], acc[mt][2*p+1][3],
                             a[mt][0], a[mt][1], a[mt][2], a[mt][3], b[p][2], b[p][3]);
                }
        }
        __syncthreads();
        if (kb < 2) {
            if (kb == 0) PREFETCH(2, 0); else PREFETCH(3, 1);
        }
    }
#undef PREFETCH

    const float INV_T = 1.0f / 0.07f;
    const int g  = lane >> 2;
    const int t4 = lane & 3;

    // ---- park z (scaled) in smem for pass 2 (off-diagonal tiles only) ----
    float* zs = reinterpret_cast<float*>(dynsmem);   // [128][ZSTR] fp32 (66.6 KB)
    if (offdiag) {
        #pragma unroll
        for (int mt = 0; mt < 2; ++mt)
            #pragma unroll
            for (int hi = 0; hi < 2; ++hi) {
                const int r = warpM * 32 + mt * 16 + hi * 8 + g;
                #pragma unroll
                for (int nt = 0; nt < 8; ++nt) {
                    const int c = warpN * 64 + nt * 8 + t4 * 2;
                    float2 v = make_float2(acc[mt][nt][hi * 2 + 0] * INV_T,
                                           acc[mt][nt][hi * 2 + 1] * INV_T);
                    *reinterpret_cast<float2*>(&zs[r * ZSTR + c]) = v;
                }
            }
        __syncthreads();
    }

    // ---- pass 1: rows of bi, mask tile (bi,bj), z from registers ----
    {
        float S1[4] = {0.f, 0.f, 0.f, 0.f};
        float P [4] = {0.f, 0.f, 0.f, 0.f};
        float NG[4] = {0.f, 0.f, 0.f, 0.f};

        #pragma unroll
        for (int mt = 0; mt < 2; ++mt) {
            #pragma unroll
            for (int hi = 0; hi < 2; ++hi) {
                const int ri   = mt * 2 + hi;
                const int grow = rowBase + warpM * 32 + mt * 16 + hi * 8 + g;
                const float* pmRow = pm + (size_t)grow * N;
                const float* nmRow = nm + (size_t)grow * N;
                float2 pv[8], nv[8];
                #pragma unroll
                for (int nt = 0; nt < 8; ++nt) {
                    const int gcol = colBase + warpN * 64 + nt * 8 + t4 * 2;
                    pv[nt] = *reinterpret_cast<const float2*>(pmRow + gcol);
                    nv[nt] = *reinterpret_cast<const float2*>(nmRow + gcol);
                }
                #pragma unroll
                for (int nt = 0; nt < 8; ++nt) {
                    const int gcol = colBase + warpN * 64 + nt * 8 + t4 * 2;
                    float p0 = pv[nt].x, p1 = pv[nt].y;
                    float n0 = nv[nt].x, n1 = nv[nt].y;
                    if (grow == gcol)     { p0 = 0.f; n0 = 0.f; }
                    if (grow == gcol + 1) { p1 = 0.f; n1 = 0.f; }
                    const float z0 = acc[mt][nt][hi * 2 + 0] * INV_T;
                    const float z1 = acc[mt][nt][hi * 2 + 1] * INV_T;
                    S1[ri] += p0 * z0 + p1 * z1;
                    P [ri] += p0 + p1;
                    NG[ri] += n0 * __expf(z0) + n1 * __expf(z1);
                }
            }
        }

        #pragma unroll
        for (int ri = 0; ri < 4; ++ri) {
            S1[ri] += __shfl_xor_sync(0xffffffffu, S1[ri], 1);
            S1[ri] += __shfl_xor_sync(0xffffffffu, S1[ri], 2);
            P [ri] += __shfl_xor_sync(0xffffffffu, P [ri], 1);
            P [ri] += __shfl_xor_sync(0xffffffffu, P [ri], 2);
            NG[ri] += __shfl_xor_sync(0xffffffffu, NG[ri], 1);
            NG[ri] += __shfl_xor_sync(0xffffffffu, NG[ri], 2);
        }

        if (t4 == 0) {
            const int cs = bj * 2 + warpN;
            #pragma unroll
            for (int ri = 0; ri < 4; ++ri) {
                const int mt = ri >> 1, hi = ri & 1;
                const int grow = rowBase + warpM * 32 + mt * 16 + hi * 8 + g;
                g_part[0][cs][grow] = S1[ri];
                g_part[1][cs][grow] = P[ri];
                g_part[2][cs][grow] = NG[ri];
            }
        }
    }

    // ---- pass 2: rows of bj, mask tile (bj,bi), z^T from smem ----
    if (offdiag) {
        const int jr = tid >> 1;               // local row in bj block
        const int h  = tid & 1;                // col half of bi block
        const int grow = colBase + jr;
        const float4* pmRow = reinterpret_cast<const float4*>(pm + (size_t)grow * N + rowBase + h * 64);
        const float4* nmRow = reinterpret_cast<const float4*>(nm + (size_t)grow * N + rowBase + h * 64);

        float s1 = 0.f, pp = 0.f, ng = 0.f;
        #pragma unroll 4
        for (int k = 0; k < 16; ++k) {
            const float4 pv = pmRow[k];
            const float4 nv = nmRow[k];
            const int i0 = h * 64 + k * 4;
            const float z0 = zs[(i0 + 0) * ZSTR + jr];
            const float z1 = zs[(i0 + 1) * ZSTR + jr];
            const float z2 = zs[(i0 + 2) * ZSTR + jr];
            const float z3 = zs[(i0 + 3) * ZSTR + jr];
            s1 += pv.x * z0 + pv.y * z1 + pv.z * z2 + pv.w * z3;
            pp += pv.x + pv.y + pv.z + pv.w;
            ng += nv.x * __expf(z0) + nv.y * __expf(z1)
                + nv.z * __expf(z2) + nv.w * __expf(z3);
        }
        const int cs = bi * 2 + h;
        g_part[0][cs][grow] = s1;
        g_part[1][cs][grow] = pp;
        g_part[2][cs][grow] = ng;
    }
}

// ---------------------------------------------------------------------------
// Kernel D: per-row finalize + full reduction (last block finishes).
// 64 blocks x 256 threads: 64 rows/block, 4 slot-groups of 16 per row.
// ---------------------------------------------------------------------------
__global__ __launch_bounds__(256) void finalize_kernel(float* __restrict__ out) {
    const int r   = threadIdx.x & 63;          // row within block
    const int p   = threadIdx.x >> 6;          // slot group 0..3
    const int row = blockIdx.x * 64 + r;

    float s1 = 0.f, pp = 0.f, ng = 0.f;
    #pragma unroll
    for (int c = p * 16; c < p * 16 + 16; ++c) {
        s1 += g_part[0][c][row];
        pp += g_part[1][c][row];
        ng += g_part[2][c][row];
    }

    __shared__ float sh[3][4][64];
    sh[0][p][r] = s1; sh[1][p][r] = pp; sh[2][p][r] = ng;
    __syncthreads();

    __shared__ float st[64];
    if (p == 0) {
        s1 = sh[0][0][r] + sh[0][1][r] + sh[0][2][r] + sh[0][3][r];
        pp = sh[1][0][r] + sh[1][1][r] + sh[1][2][r] + sh[1][3][r];
        ng = sh[2][0][r] + sh[2][1][r] + sh[2][2][r] + sh[2][3][r];
        float term = 0.f;
        if (pp > 0.5f) term = (s1 - pp * logf(ng)) / pp;
        st[r] = term;
    }
    __syncthreads();

    __shared__ unsigned s_last;
    if (threadIdx.x < 32) {
        float v = st[threadIdx.x] + st[threadIdx.x + 32];
        #pragma unroll
        for (int off = 16; off > 0; off >>= 1)
            v += __shfl_xor_sync(0xffffffffu, v, off);
        if (threadIdx.x == 0) {
            g_bsum[blockIdx.x] = v;
            __threadfence();
            s_last = atomicAdd(&g_cnt, 1u);
        }
    }
    __syncthreads();

    if (s_last == 63 && threadIdx.x < 32) {
        __threadfence();
        volatile float* vb = g_bsum;
        float v = vb[threadIdx.x] + vb[threadIdx.x + 32];
        #pragma unroll
        for (int off = 16; off > 0; off >>= 1)
            v += __shfl_xor_sync(0xffffffffu, v, off);
        if (threadIdx.x == 0) {
            out[0] = -(v / (float)N);
            g_cnt = 0;   // reset for next graph replay
        }
    }
}

// ---------------------------------------------------------------------------
extern "C" void kernel_launch(void* const* d_in, const int* in_sizes, int n_in,
                              void* d_out, int out_size) {
    (void)in_sizes; (void)n_in; (void)out_size;
    const float* f  = (const float*)d_in[0];
    const float* pm = (const float*)d_in[1];
    const float* nm = (const float*)d_in[2];

    static bool attr_set = false;
    if (!attr_set) {
        cudaFuncSetAttribute(main_kernel, cudaFuncAttributeMaxDynamicSharedMemorySize,
                             4 * TILE_HW * 2);
        attr_set = true;
    }

    norm_kernel<<<N / 4, 128>>>(f);
    main_kernel<<<NCTA, 256, 4 * TILE_HW * 2>>>(pm, nm);
    finalize_kernel<<<64, 256>>>((float*)d_out);
}